// round 4
// baseline (speedup 1.0000x reference)
#include <cuda_runtime.h>
#include <cuda_bf16.h>
#include <cstdint>
#include <math.h>

// ---------------- problem constants ----------------
#define BATCH    1024
#define TSTEPS   80
#define DIM      512
#define CLS      78
#define BLANK    77
#define PRED_LEN 30
#define ROWS     (BATCH * TSTEPS)     // 81920

#define TILE_M   160                  // 2 batch items per tile
#define NTILES   (ROWS / TILE_M)      // 512
#define NCTAS    148
#define THREADS  320                  // 10 warps: rs in [0,5) x jh in [0,2)
#define NKC      16                   // k32 chunks (512/32)

// ---------------- smem layout (bytes) ----------------
// B rows: n in [0,80), stride 1088 (1024 data + 64 pad, conflict-free LDS.128)
#define B_STRIDE  1088
#define B_BYTES   (80 * B_STRIDE)       // 87040 each (hi, lo)
#define SM_BHI    0
#define SM_BLO    B_BYTES               // 87040
#define SM_SBEST  (2 * B_BYTES)         // 174080 : int sbest[160]
#define SM_A      (SM_SBEST + 640)      // 174720 : union{ A bufs , logits }
// A buf: [hi 160*64][lo 160*64] = 20480 per buffer, 2 buffers = 40960
// logits: 160 rows * 320B = 51200  -> region size 51200
#define SM_TOTAL  (SM_A + 51200)        // 225920

__device__ __forceinline__ int kperm(int k) {
    int grp = k >> 5, r = k & 31;
    int s = r >> 4;
    int j = r & 15;
    int t = (j & 7) >> 1;
    int idx = (k & 1) | ((j >> 3) << 1);
    return grp * 32 + t * 8 + s * 4 + idx;   // u16 index
}

__device__ __forceinline__ uint32_t pack_bf16(float a, float b) {
    __nv_bfloat16 ha = __float2bfloat16_rn(a);
    __nv_bfloat16 hb = __float2bfloat16_rn(b);
    return (uint32_t)__bfloat16_as_ushort(ha) |
           ((uint32_t)__bfloat16_as_ushort(hb) << 16);
}

__device__ __forceinline__ void split4(float4 f, uint32_t& hxy, uint32_t& hzw,
                                       uint32_t& lxy, uint32_t& lzw) {
    hxy = pack_bf16(f.x, f.y);
    hzw = pack_bf16(f.z, f.w);
    float hx = __bfloat162float(__float2bfloat16_rn(f.x));
    float hy = __bfloat162float(__float2bfloat16_rn(f.y));
    float hz = __bfloat162float(__float2bfloat16_rn(f.z));
    float hw = __bfloat162float(__float2bfloat16_rn(f.w));
    lxy = pack_bf16(f.x - hx, f.y - hy);
    lzw = pack_bf16(f.z - hz, f.w - hw);
}

__device__ __forceinline__ void mma16816(float* c, uint32_t a0, uint32_t a1,
                                         uint32_t a2, uint32_t a3,
                                         uint32_t b0, uint32_t b1) {
    asm volatile(
        "mma.sync.aligned.m16n8k16.row.col.f32.bf16.bf16.f32 "
        "{%0,%1,%2,%3}, {%4,%5,%6,%7}, {%8,%9}, {%0,%1,%2,%3};"
        : "+f"(c[0]), "+f"(c[1]), "+f"(c[2]), "+f"(c[3])
        : "r"(a0), "r"(a1), "r"(a2), "r"(a3), "r"(b0), "r"(b1));
}

// ---------------------------------------------------------------------------
// Single fused kernel: W prep + bf16-split HMMA GEMM + softmax + argmax + CTC
// ---------------------------------------------------------------------------
__global__ void __launch_bounds__(THREADS, 1)
ctc_fused_kernel(const float* __restrict__ feat,
                 const float* __restrict__ Wg,
                 const float* __restrict__ bg,
                 float* __restrict__ out)
{
    extern __shared__ char sm[];
    const int tid  = threadIdx.x;
    const int lane = tid & 31;
    const int warp = tid >> 5;
    const int g    = lane >> 2;
    const int t    = lane & 3;
    const int rs   = warp % 5;     // row-stripe pair: rows [32rs, 32rs+32)
    const int jh   = warp / 5;     // col half: cols [40jh, 40jh+40)

    // ---- build B = W^T as bf16 hi/lo in k-permuted layout (coalesced read) ----
    for (int idx = tid; idx < 80 * DIM; idx += THREADS) {
        int k = idx / 80;
        int n = idx - k * 80;
        float v = (n < CLS) ? Wg[k * CLS + n] : 0.0f;
        __nv_bfloat16 h = __float2bfloat16_rn(v);
        __nv_bfloat16 l = __float2bfloat16_rn(v - __bfloat162float(h));
        int byte = n * B_STRIDE + kperm(k) * 2;
        *(uint16_t*)(sm + SM_BHI + byte) = __bfloat16_as_ushort(h);
        *(uint16_t*)(sm + SM_BLO + byte) = __bfloat16_as_ushort(l);
    }

    // per-thread bias for cols 40jh + 8j + 2t + e
    float bb[5][2];
    #pragma unroll
    for (int j = 0; j < 5; j++) {
        int col = 40 * jh + 8 * j + 2 * t;
        bb[j][0] = (col     < CLS) ? bg[col]     : 0.0f;
        bb[j][1] = (col + 1 < CLS) ? bg[col + 1] : 0.0f;
    }
    __syncthreads();

    const float4* f4 = (const float4*)feat;

    for (int tile = blockIdx.x; tile < NTILES; tile += gridDim.x) {
        const size_t tb = (size_t)tile * TILE_M;

        float c[2][5][4];
        #pragma unroll
        for (int rt = 0; rt < 2; rt++)
            #pragma unroll
            for (int j = 0; j < 5; j++)
                { c[rt][j][0]=0.f; c[rt][j][1]=0.f; c[rt][j][2]=0.f; c[rt][j][3]=0.f; }

        // ---- prologue: produce chunk 0 into buf 0 ----
        float4 f[4];
        #pragma unroll
        for (int i = 0; i < 4; i++) {
            int fidx = tid + THREADS * i;
            f[i] = f4[(tb + (fidx >> 3)) * 128 + (fidx & 7)];
        }
        #pragma unroll
        for (int i = 0; i < 4; i++) {
            int fidx = tid + THREADS * i;
            int row = fidx >> 3, q = fidx & 7;
            int off = (q & 1) * 32 + (q >> 1) * 4;
            char* hb = sm + SM_A + row * 64 + off;
            uint32_t hxy, hzw, lxy, lzw;
            split4(f[i], hxy, hzw, lxy, lzw);
            *(uint32_t*)(hb)              = hxy;
            *(uint32_t*)(hb + 16)         = hzw;
            *(uint32_t*)(hb + 10240)      = lxy;
            *(uint32_t*)(hb + 10240 + 16) = lzw;
        }
        __syncthreads();

        // ---- mainloop: 16 chunks of k32, ping-pong bufs, 1 barrier each ----
        for (int kc = 0; kc < NKC; kc++) {
            if (kc < NKC - 1) {
                #pragma unroll
                for (int i = 0; i < 4; i++) {
                    int fidx = tid + THREADS * i;
                    f[i] = f4[(tb + (fidx >> 3)) * 128 + (kc + 1) * 8 + (fidx & 7)];
                }
            }
            // consume buf kc&1
            {
                const char* A = sm + SM_A + (kc & 1) * 20480;
                uint4 ah[2][2], al[2][2];
                #pragma unroll
                for (int rt = 0; rt < 2; rt++) {
                    const char* ap = A + (rs * 32 + rt * 16 + g) * 64 + t * 16;
                    ah[rt][0] = *(const uint4*)(ap);
                    ah[rt][1] = *(const uint4*)(ap + 8 * 64);
                    al[rt][0] = *(const uint4*)(ap + 10240);
                    al[rt][1] = *(const uint4*)(ap + 10240 + 8 * 64);
                }
                const int boff = kc * 64 + t * 16;
                #pragma unroll
                for (int j = 0; j < 5; j++) {
                    const int n = 40 * jh + 8 * j + g;
                    uint4 bh = *(const uint4*)(sm + SM_BHI + n * B_STRIDE + boff);
                    uint4 bl = *(const uint4*)(sm + SM_BLO + n * B_STRIDE + boff);
                    #pragma unroll
                    for (int rt = 0; rt < 2; rt++) {
                        float* cc = c[rt][j];
                        // k16 step 0
                        mma16816(cc, ah[rt][0].x, ah[rt][1].x, ah[rt][0].y, ah[rt][1].y, bh.x, bh.y);
                        mma16816(cc, ah[rt][0].x, ah[rt][1].x, ah[rt][0].y, ah[rt][1].y, bl.x, bl.y);
                        mma16816(cc, al[rt][0].x, al[rt][1].x, al[rt][0].y, al[rt][1].y, bh.x, bh.y);
                        // k16 step 1
                        mma16816(cc, ah[rt][0].z, ah[rt][1].z, ah[rt][0].w, ah[rt][1].w, bh.z, bh.w);
                        mma16816(cc, ah[rt][0].z, ah[rt][1].z, ah[rt][0].w, ah[rt][1].w, bl.z, bl.w);
                        mma16816(cc, al[rt][0].z, al[rt][1].z, al[rt][0].w, al[rt][1].w, bh.z, bh.w);
                    }
                }
            }
            // produce chunk kc+1 into buf (kc+1)&1
            if (kc < NKC - 1) {
                char* A = sm + SM_A + ((kc + 1) & 1) * 20480;
                #pragma unroll
                for (int i = 0; i < 4; i++) {
                    int fidx = tid + THREADS * i;
                    int row = fidx >> 3, q = fidx & 7;
                    int off = (q & 1) * 32 + (q >> 1) * 4;
                    char* hb = A + row * 64 + off;
                    uint32_t hxy, hzw, lxy, lzw;
                    split4(f[i], hxy, hzw, lxy, lzw);
                    *(uint32_t*)(hb)              = hxy;
                    *(uint32_t*)(hb + 16)         = hzw;
                    *(uint32_t*)(hb + 10240)      = lxy;
                    *(uint32_t*)(hb + 10240 + 16) = lzw;
                }
            }
            __syncthreads();
        }

        // ---- stage bias-added logits to smem [160][80] fp32 (stride 320B) ----
        #pragma unroll
        for (int rt = 0; rt < 2; rt++) {
            const int row0 = rs * 32 + rt * 16 + g;
            #pragma unroll
            for (int j = 0; j < 5; j++) {
                const int col = 40 * jh + 8 * j + 2 * t;
                *(float2*)(sm + SM_A + row0 * 320 + col * 4) =
                    make_float2(c[rt][j][0] + bb[j][0], c[rt][j][1] + bb[j][1]);
                *(float2*)(sm + SM_A + (row0 + 8) * 320 + col * 4) =
                    make_float2(c[rt][j][2] + bb[j][0], c[rt][j][3] + bb[j][1]);
            }
        }
        __syncthreads();

        // ---- row-parallel softmax + argmax: thread pair per row ----
        {
            const int r = tid >> 1;
            const int h = tid & 1;
            const float4* lp = (const float4*)(sm + SM_A + r * 320 + h * 160);
            float v[40];
            #pragma unroll
            for (int u = 0; u < 10; u++) {
                float4 w = lp[u];
                v[4*u] = w.x; v[4*u+1] = w.y; v[4*u+2] = w.z; v[4*u+3] = w.w;
            }
            float m = -INFINITY; int bi = 0;
            #pragma unroll
            for (int idx = 0; idx < 40; idx++) {
                int col = 40 * h + idx;
                if (col < CLS && v[idx] > m) { m = v[idx]; bi = col; }
            }
            {
                float om = __shfl_xor_sync(0xffffffffu, m, 1);
                int   oi = __shfl_xor_sync(0xffffffffu, bi, 1);
                if (om > m || (om == m && oi < bi)) { m = om; bi = oi; }
            }
            float s = 0.f;
            #pragma unroll
            for (int idx = 0; idx < 40; idx++) {
                int col = 40 * h + idx;
                float e = (col < CLS) ? __expf(v[idx] - m) : 0.f;
                v[idx] = e; s += e;
            }
            s += __shfl_xor_sync(0xffffffffu, s, 1);
            const float inv = 1.0f / s;

            float* orow = out + (tb + r) * CLS + 40 * h;
            const int npair = h ? 19 : 20;
            #pragma unroll
            for (int p = 0; p < 20; p++)
                if (p < npair)
                    *(float2*)(orow + 2 * p) = make_float2(v[2*p] * inv, v[2*p+1] * inv);
            if (h == 0) ((int*)(sm + SM_SBEST))[r] = bi;
        }
        __syncthreads();

        // ---- CTC greedy decode: warps 0,1 -> batch items 2*tile, 2*tile+1 ----
        if (warp < 2) {
            const int* bp = (const int*)(sm + SM_SBEST) + warp * TSTEPS;
            const unsigned full = 0xffffffffu;
            int v0 = bp[lane];
            int v1 = bp[lane + 32];
            int v2 = (lane < 16) ? bp[lane + 64] : BLANK;

            int p0 = __shfl_up_sync(full, v0, 1); if (lane == 0) p0 = -1;
            int t0 = __shfl_sync(full, v0, 31);
            int p1 = __shfl_up_sync(full, v1, 1); if (lane == 0) p1 = t0;
            int t1 = __shfl_sync(full, v1, 31);
            int p2 = __shfl_up_sync(full, v2, 1); if (lane == 0) p2 = t1;

            bool k0 = (v0 != BLANK) && (v0 != p0);
            bool k1 = (v1 != BLANK) && (v1 != p1);
            bool k2 = (lane < 16) && (v2 != BLANK) && (v2 != p2);
            unsigned m0 = __ballot_sync(full, k0);
            unsigned m1 = __ballot_sync(full, k1);
            unsigned m2 = __ballot_sync(full, k2);
            int c0 = __popc(m0), c1 = __popc(m1);
            unsigned lt = (1u << lane) - 1u;

            float* ob = out + (size_t)ROWS * CLS + (size_t)(tile * 2 + warp) * PRED_LEN;
            if (lane < PRED_LEN) ob[lane] = -1.0f;
            __syncwarp();
            if (k0) { int p = __popc(m0 & lt);           if (p < PRED_LEN) ob[p] = (float)v0; }
            if (k1) { int p = c0 + __popc(m1 & lt);      if (p < PRED_LEN) ob[p] = (float)v1; }
            if (k2) { int p = c0 + c1 + __popc(m2 & lt); if (p < PRED_LEN) ob[p] = (float)v2; }
        }
        // no barrier needed: next producer writes A bufs (logits dead), sbest
        // untouched until next tile's post-reader phase... but reader writes
        // sbest before decode reads it; keep one barrier for cross-tile safety:
        __syncthreads();
    }
}

// ---------------------------------------------------------------------------
extern "C" void kernel_launch(void* const* d_in, const int* in_sizes, int n_in,
                              void* d_out, int out_size)
{
    const float* feat = (const float*)d_in[0];
    const float* W    = (const float*)d_in[1];
    const float* b    = (const float*)d_in[2];
    float* out        = (float*)d_out;

    cudaFuncSetAttribute(ctc_fused_kernel,
                         cudaFuncAttributeMaxDynamicSharedMemorySize, SM_TOTAL);
    ctc_fused_kernel<<<NCTAS, THREADS, SM_TOTAL>>>(feat, W, b, out);
}

// round 5
// speedup vs baseline: 1.2615x; 1.2615x over previous
#include <cuda_runtime.h>
#include <cuda_bf16.h>
#include <cstdint>
#include <math.h>

// ---------------- problem constants ----------------
#define BATCH    1024
#define TSTEPS   80
#define DIM      512
#define CLS      78
#define BLANK    77
#define PRED_LEN 30
#define ROWS     (BATCH * TSTEPS)     // 81920

#define TILE_M   128
#define NTILES   (ROWS / TILE_M)      // 640
#define NCTAS    148
#define THREADS  512                  // 16 warps: rs = warp>>1 (8 stripes of 16 rows), jh = warp&1
#define NKC      16                   // k32 chunks (512/32)
#define NSTAGE   3
#define STAGE_BYTES 16384             // 128 rows x 32 k x fp32

// ---------------- smem layout (bytes) ----------------
#define B_STRIDE  1088                // 1024 data + 64 pad
#define B_BYTES   (80 * B_STRIDE)     // 87040 each
#define SM_BHI    0
#define SM_BLO    B_BYTES
#define SM_A      (2 * B_BYTES)       // 174080 : 3 stage bufs (union: logits 128x320B=40960)
#define SM_TOTAL  (SM_A + NSTAGE * STAGE_BYTES)   // 223232

__device__ int g_best[ROWS];

// B k-permutation matched to contiguous-fp32 A fragments:
// logical k -> u16 pos: grp = k>>5, r = k&31, s = r>>4, t = (r&15)>>2, idx = r&3
// pos = grp*32 + t*8 + s*4 + idx  (thread t's uint4 at grp*64 + t*16 holds both k16 steps)
__device__ __forceinline__ int kperm(int k) {
    int grp = k >> 5, r = k & 31;
    int s = r >> 4;
    int t = (r & 15) >> 2;
    int idx = r & 3;
    return grp * 32 + t * 8 + s * 4 + idx;
}

__device__ __forceinline__ uint32_t pack_bf16(float a, float b) {
    __nv_bfloat16 ha = __float2bfloat16_rn(a);
    __nv_bfloat16 hb = __float2bfloat16_rn(b);
    return (uint32_t)__bfloat16_as_ushort(ha) |
           ((uint32_t)__bfloat16_as_ushort(hb) << 16);
}

// split float pair into hi bf16x2 and lo bf16x2
__device__ __forceinline__ void split2(float a, float b, uint32_t& h, uint32_t& l) {
    h = pack_bf16(a, b);
    float ha = __uint_as_float(h << 16);
    float hb = __uint_as_float(h & 0xffff0000u);
    l = pack_bf16(a - ha, b - hb);
}

__device__ __forceinline__ void mma16816(float* c, uint32_t a0, uint32_t a1,
                                         uint32_t a2, uint32_t a3,
                                         uint32_t b0, uint32_t b1) {
    asm volatile(
        "mma.sync.aligned.m16n8k16.row.col.f32.bf16.bf16.f32 "
        "{%0,%1,%2,%3}, {%4,%5,%6,%7}, {%8,%9}, {%0,%1,%2,%3};"
        : "+f"(c[0]), "+f"(c[1]), "+f"(c[2]), "+f"(c[3])
        : "r"(a0), "r"(a1), "r"(a2), "r"(a3), "r"(b0), "r"(b1));
}

__device__ __forceinline__ void cp_async16(void* dst_smem, const void* src) {
    uint32_t d = (uint32_t)__cvta_generic_to_shared(dst_smem);
    asm volatile("cp.async.cg.shared.global [%0], [%1], 16;" :: "r"(d), "l"(src));
}

// issue one k32 stage: 128 rows x 32 floats (128B/row), XOR-swizzled by row parity
__device__ __forceinline__ void issue_stage(const float* __restrict__ feat,
                                            size_t tb, int kc, char* buf, int tid) {
    #pragma unroll
    for (int i = 0; i < 2; i++) {
        int slot = tid + THREADS * i;           // 1024 slots of 16B
        int row = slot >> 3, q = slot & 7;
        const float* src = feat + (tb + row) * DIM + kc * 32 + q * 4;
        cp_async16(buf + row * 128 + ((q * 16) ^ ((row & 1) << 6)), src);
    }
}

// ---------------------------------------------------------------------------
// Main: cp.async-pipelined bf16-split HMMA GEMM + bias + softmax + argmax
// ---------------------------------------------------------------------------
__global__ void __launch_bounds__(THREADS, 1)
ctc_main_kernel(const float* __restrict__ feat,
                const float* __restrict__ Wg,
                const float* __restrict__ bg,
                float* __restrict__ out)
{
    extern __shared__ char sm[];
    const int tid  = threadIdx.x;
    const int lane = tid & 31;
    const int warp = tid >> 5;
    const int g    = lane >> 2;
    const int t    = lane & 3;
    const int rs   = warp >> 1;     // row stripe: rows [16rs, 16rs+16)
    const int jh   = warp & 1;      // col half: cols [40jh, 40jh+40)

    // ---- build B = W^T bf16 hi/lo, k-permuted, zero-padded to 80 cols ----
    for (int idx = tid; idx < 80 * DIM; idx += THREADS) {
        int k = idx / 80;
        int n = idx - k * 80;
        float v = (n < CLS) ? Wg[k * CLS + n] : 0.0f;
        __nv_bfloat16 h = __float2bfloat16_rn(v);
        __nv_bfloat16 l = __float2bfloat16_rn(v - __bfloat162float(h));
        int byte = n * B_STRIDE + kperm(k) * 2;
        *(uint16_t*)(sm + SM_BHI + byte) = __bfloat16_as_ushort(h);
        *(uint16_t*)(sm + SM_BLO + byte) = __bfloat16_as_ushort(l);
    }
    float bb[5][2];
    #pragma unroll
    for (int j = 0; j < 5; j++) {
        int col = 40 * jh + 8 * j + 2 * t;
        bb[j][0] = (col     < CLS) ? bg[col]     : 0.0f;
        bb[j][1] = (col + 1 < CLS) ? bg[col + 1] : 0.0f;
    }
    __syncthreads();

    char* const smA = sm + SM_A;
    const int aswz = (g & 1) << 6;

    for (int tile = blockIdx.x; tile < NTILES; tile += gridDim.x) {
        const size_t tb = (size_t)tile * TILE_M;

        float c[5][4];
        #pragma unroll
        for (int j = 0; j < 5; j++)
            { c[j][0] = 0.f; c[j][1] = 0.f; c[j][2] = 0.f; c[j][3] = 0.f; }

        // prologue: stages 0,1 in flight
        issue_stage(feat, tb, 0, smA, tid);
        asm volatile("cp.async.commit_group;" ::: "memory");
        issue_stage(feat, tb, 1, smA + STAGE_BYTES, tid);
        asm volatile("cp.async.commit_group;" ::: "memory");

        for (int kc = 0; kc < NKC; kc++) {
            asm volatile("cp.async.wait_group 1;" ::: "memory");
            __syncthreads();
            if (kc + 2 < NKC)
                issue_stage(feat, tb, kc + 2, smA + ((kc + 2) % NSTAGE) * STAGE_BYTES, tid);
            asm volatile("cp.async.commit_group;" ::: "memory");

            // ---- consume stage kc ----
            const char* A = smA + (kc % NSTAGE) * STAGE_BYTES;
            const int r0 = rs * 16 + g;
            float4 F[2][2];             // [row-half rr][k16 step s]
            #pragma unroll
            for (int s = 0; s < 2; s++) {
                int off = (64 * s + 16 * t) ^ aswz;
                F[0][s] = *(const float4*)(A + r0 * 128 + off);
                F[1][s] = *(const float4*)(A + (r0 + 8) * 128 + off);
            }
            uint32_t AH[2][2][2], AL[2][2][2];   // [rr][s][half]
            #pragma unroll
            for (int rr = 0; rr < 2; rr++)
                #pragma unroll
                for (int s = 0; s < 2; s++) {
                    split2(F[rr][s].x, F[rr][s].y, AH[rr][s][0], AL[rr][s][0]);
                    split2(F[rr][s].z, F[rr][s].w, AH[rr][s][1], AL[rr][s][1]);
                }

            const int boff = kc * 64 + t * 16;
            #pragma unroll
            for (int j = 0; j < 5; j++) {
                const int n = 40 * jh + 8 * j + g;
                uint4 bh = *(const uint4*)(sm + SM_BHI + n * B_STRIDE + boff);
                uint4 bl = *(const uint4*)(sm + SM_BLO + n * B_STRIDE + boff);
                // s = 0 : b pairs (x, y)
                mma16816(c[j], AH[0][0][0], AH[1][0][0], AH[0][0][1], AH[1][0][1], bh.x, bh.y);
                mma16816(c[j], AH[0][0][0], AH[1][0][0], AH[0][0][1], AH[1][0][1], bl.x, bl.y);
                mma16816(c[j], AL[0][0][0], AL[1][0][0], AL[0][0][1], AL[1][0][1], bh.x, bh.y);
                // s = 1 : b pairs (z, w)
                mma16816(c[j], AH[0][1][0], AH[1][1][0], AH[0][1][1], AH[1][1][1], bh.z, bh.w);
                mma16816(c[j], AH[0][1][0], AH[1][1][0], AH[0][1][1], AH[1][1][1], bl.z, bl.w);
                mma16816(c[j], AL[0][1][0], AL[1][1][0], AL[0][1][1], AL[1][1][1], bh.z, bh.w);
            }
        }
        __syncthreads();   // all MMA reads of stage bufs done before logits staging

        // ---- stage bias-added logits [128][80] fp32 into A region ----
        {
            float* L = (float*)smA;
            const int row0 = rs * 16 + g;
            #pragma unroll
            for (int j = 0; j < 5; j++) {
                const int col = 40 * jh + 8 * j + 2 * t;
                *(float2*)(L + row0 * 80 + col) =
                    make_float2(c[j][0] + bb[j][0], c[j][1] + bb[j][1]);
                *(float2*)(L + (row0 + 8) * 80 + col) =
                    make_float2(c[j][2] + bb[j][0], c[j][3] + bb[j][1]);
            }
        }
        __syncthreads();

        // ---- softmax + argmax: 4 threads per row, 20 cols each ----
        {
            const int r = tid >> 2;
            const int h = tid & 3;
            const float* L = (const float*)smA;
            const float4* lp = (const float4*)(L + r * 80 + h * 20);
            float v[20];
            #pragma unroll
            for (int u = 0; u < 5; u++) {
                float4 w = lp[u];
                v[4*u] = w.x; v[4*u+1] = w.y; v[4*u+2] = w.z; v[4*u+3] = w.w;
            }
            float m = -INFINITY; int bi = 0;
            #pragma unroll
            for (int idx = 0; idx < 20; idx++) {
                int col = 20 * h + idx;
                if (col < CLS && v[idx] > m) { m = v[idx]; bi = col; }
            }
            #pragma unroll
            for (int d = 1; d <= 2; d <<= 1) {
                float om = __shfl_xor_sync(0xffffffffu, m, d);
                int   oi = __shfl_xor_sync(0xffffffffu, bi, d);
                if (om > m || (om == m && oi < bi)) { m = om; bi = oi; }
            }
            float s = 0.f;
            #pragma unroll
            for (int idx = 0; idx < 20; idx++) {
                int col = 20 * h + idx;
                float e = (col < CLS) ? __expf(v[idx] - m) : 0.f;
                v[idx] = e; s += e;
            }
            #pragma unroll
            for (int d = 1; d <= 2; d <<= 1)
                s += __shfl_xor_sync(0xffffffffu, s, d);
            const float inv = 1.0f / s;

            float* orow = out + (tb + r) * CLS + 20 * h;
            const int npair = (h == 3) ? 9 : 10;
            #pragma unroll
            for (int p = 0; p < 10; p++)
                if (p < npair)
                    *(float2*)(orow + 2 * p) = make_float2(v[2*p] * inv, v[2*p+1] * inv);
            if (h == 0) g_best[tb + r] = bi;
        }
        __syncthreads();   // logits consumed -> next tile may overwrite stage bufs
    }
}

// ---------------------------------------------------------------------------
// CTC greedy decode: one warp per batch row, ballot compaction
// ---------------------------------------------------------------------------
__global__ void ctc_decode_kernel(float* __restrict__ out)
{
    const int gw = (blockIdx.x * blockDim.x + threadIdx.x) >> 5;
    const int lane = threadIdx.x & 31;
    const int wl = threadIdx.x >> 5;
    __shared__ float buf[8][32];
    if (gw >= BATCH) return;

    const int* bp = g_best + gw * TSTEPS;
    const unsigned full = 0xffffffffu;
    int v0 = bp[lane];
    int v1 = bp[lane + 32];
    int v2 = (lane < 16) ? bp[lane + 64] : BLANK;

    int p0 = __shfl_up_sync(full, v0, 1); if (lane == 0) p0 = -1;
    int t0 = __shfl_sync(full, v0, 31);
    int p1 = __shfl_up_sync(full, v1, 1); if (lane == 0) p1 = t0;
    int t1 = __shfl_sync(full, v1, 31);
    int p2 = __shfl_up_sync(full, v2, 1); if (lane == 0) p2 = t1;

    bool k0 = (v0 != BLANK) && (v0 != p0);
    bool k1 = (v1 != BLANK) && (v1 != p1);
    bool k2 = (lane < 16) && (v2 != BLANK) && (v2 != p2);
    unsigned m0 = __ballot_sync(full, k0);
    unsigned m1 = __ballot_sync(full, k1);
    unsigned m2 = __ballot_sync(full, k2);
    int c0 = __popc(m0), c1 = __popc(m1);
    unsigned lt = (1u << lane) - 1u;

    buf[wl][lane] = -1.0f;
    __syncwarp();
    if (k0) { int p = __popc(m0 & lt);           if (p < PRED_LEN) buf[wl][p] = (float)v0; }
    if (k1) { int p = c0 + __popc(m1 & lt);      if (p < PRED_LEN) buf[wl][p] = (float)v1; }
    if (k2) { int p = c0 + c1 + __popc(m2 & lt); if (p < PRED_LEN) buf[wl][p] = (float)v2; }
    __syncwarp();
    if (lane < PRED_LEN)
        out[(size_t)ROWS * CLS + (size_t)gw * PRED_LEN + lane] = buf[wl][lane];
}

// ---------------------------------------------------------------------------
extern "C" void kernel_launch(void* const* d_in, const int* in_sizes, int n_in,
                              void* d_out, int out_size)
{
    const float* feat = (const float*)d_in[0];
    const float* W    = (const float*)d_in[1];
    const float* b    = (const float*)d_in[2];
    float* out        = (float*)d_out;

    cudaFuncSetAttribute(ctc_main_kernel,
                         cudaFuncAttributeMaxDynamicSharedMemorySize, SM_TOTAL);
    ctc_main_kernel<<<NCTAS, THREADS, SM_TOTAL>>>(feat, W, b, out);
    ctc_decode_kernel<<<(BATCH * 32 + 255) / 256, 256>>>(out);
}

// round 6
// speedup vs baseline: 1.8573x; 1.4723x over previous
#include <cuda_runtime.h>
#include <cuda_bf16.h>
#include <cstdint>
#include <math.h>

// ---------------- problem constants ----------------
#define BATCH    1024
#define TSTEPS   80
#define DIM      512
#define CLS      78
#define BLANK    77
#define PRED_LEN 30
#define ROWS     (BATCH * TSTEPS)     // 81920

#define STRIP_M  16
#define NSTRIPS  (ROWS / STRIP_M)     // 5120
#define NCTAS    148
#define THREADS  256                  // 8 warps, each owns one 16-row strip at a time
#define NKC      16                   // k32 chunks (512/32)
#define NSTAGE   3
#define STAGE_B  2048                 // 16 rows x 32 fp32 = 2KB per stage per warp

// ---------------- smem layout (bytes) ----------------
#define B_STRIDE  1088                // 1024 data + 64 pad (conflict-free LDS.128)
#define B_BYTES   (80 * B_STRIDE)     // 87040 each (hi, lo)
#define SM_BHI    0
#define SM_BLO    B_BYTES
#define SM_A      (2 * B_BYTES)                    // 174080
#define SM_TOTAL  (SM_A + 8 * NSTAGE * STAGE_B)    // 223232

__device__ int g_strip;               // dynamic work counter (reset each launch)
__device__ int g_best[ROWS];

// B k-permutation matched to contiguous-fp32 A fragments:
// k -> u16 pos: grp=k>>5, r=k&31, s=r>>4, t=(r&15)>>2, idx=r&3
// pos = grp*32 + t*8 + s*4 + idx
__device__ __forceinline__ int kperm(int k) {
    int grp = k >> 5, r = k & 31;
    int s = r >> 4;
    int t = (r & 15) >> 2;
    int idx = r & 3;
    return grp * 32 + t * 8 + s * 4 + idx;
}

__device__ __forceinline__ uint32_t pack_bf16(float a, float b) {
    uint32_t r;
    asm("cvt.rn.satfinite.bf16x2.f32 %0, %1, %2;" : "=r"(r) : "f"(b), "f"(a));
    return r;
}

// split float pair into hi bf16x2 and lo bf16x2
__device__ __forceinline__ void split2(float a, float b, uint32_t& h, uint32_t& l) {
    h = pack_bf16(a, b);
    float ha = __uint_as_float(h << 16);
    float hb = __uint_as_float(h & 0xffff0000u);
    l = pack_bf16(a - ha, b - hb);
}

__device__ __forceinline__ void mma16816(float* c, uint32_t a0, uint32_t a1,
                                         uint32_t a2, uint32_t a3,
                                         uint32_t b0, uint32_t b1) {
    asm volatile(
        "mma.sync.aligned.m16n8k16.row.col.f32.bf16.bf16.f32 "
        "{%0,%1,%2,%3}, {%4,%5,%6,%7}, {%8,%9}, {%0,%1,%2,%3};"
        : "+f"(c[0]), "+f"(c[1]), "+f"(c[2]), "+f"(c[3])
        : "r"(a0), "r"(a1), "r"(a2), "r"(a3), "r"(b0), "r"(b1));
}

__device__ __forceinline__ void cp_async16(void* dst_smem, const void* src) {
    uint32_t d = (uint32_t)__cvta_generic_to_shared(dst_smem);
    asm volatile("cp.async.cg.shared.global [%0], [%1], 16;" :: "r"(d), "l"(src));
}

// warp-private: load 16 rows x k32 fp32 (2KB) into stage buf, slot-swizzled
__device__ __forceinline__ void issue_stage(const float* __restrict__ feat,
                                            size_t rb, int kc, char* buf, int lane) {
    #pragma unroll
    for (int i = 0; i < 4; i++) {
        int slot = lane + 32 * i;        // 128 slots of 16B
        int row = slot >> 3, q = slot & 7;
        const float* src = feat + (rb + row) * DIM + kc * 32 + q * 4;
        cp_async16(buf + row * 128 + ((q ^ ((row & 1) << 2)) << 4), src);
    }
}

// ---------------------------------------------------------------------------
// Main: barrier-free warp-autonomous bf16-split HMMA + bias+softmax+argmax
// ---------------------------------------------------------------------------
__global__ void __launch_bounds__(THREADS, 1)
ctc_main_kernel(const float* __restrict__ feat,
                const float* __restrict__ Wg,
                const float* __restrict__ bg,
                float* __restrict__ out)
{
    extern __shared__ char sm[];
    const int tid  = threadIdx.x;
    const int lane = tid & 31;
    const int warp = tid >> 5;
    const int g    = lane >> 2;
    const int t    = lane & 3;
    const unsigned full = 0xffffffffu;

    // ---- build B = W^T bf16 hi/lo, k-permuted, zero-padded to 80 cols ----
    for (int idx = tid; idx < 80 * DIM; idx += THREADS) {
        int k = idx / 80;
        int n = idx - k * 80;
        float v = (n < CLS) ? Wg[k * CLS + n] : 0.0f;
        __nv_bfloat16 h = __float2bfloat16_rn(v);
        __nv_bfloat16 l = __float2bfloat16_rn(v - __bfloat162float(h));
        int byte = n * B_STRIDE + kperm(k) * 2;
        *(uint16_t*)(sm + SM_BHI + byte) = __bfloat16_as_ushort(h);
        *(uint16_t*)(sm + SM_BLO + byte) = __bfloat16_as_ushort(l);
    }
    float bb[10][2];
    #pragma unroll
    for (int j = 0; j < 10; j++) {
        int col = 8 * j + 2 * t;
        bb[j][0] = (col     < CLS) ? bg[col]     : 0.0f;
        bb[j][1] = (col + 1 < CLS) ? bg[col + 1] : 0.0f;
    }
    __syncthreads();     // the ONLY cta-wide barrier

    char* const myA = sm + SM_A + warp * (NSTAGE * STAGE_B);

    for (;;) {
        int strip = 0;
        if (lane == 0) strip = atomicAdd(&g_strip, 1);
        strip = __shfl_sync(full, strip, 0);
        if (strip >= NSTRIPS) break;
        const size_t rb = (size_t)strip * STRIP_M;

        float c[10][4];
        #pragma unroll
        for (int j = 0; j < 10; j++)
            { c[j][0] = 0.f; c[j][1] = 0.f; c[j][2] = 0.f; c[j][3] = 0.f; }

        // prologue: 3 stages in flight
        #pragma unroll
        for (int p = 0; p < NSTAGE; p++) {
            issue_stage(feat, rb, p, myA + p * STAGE_B, lane);
            asm volatile("cp.async.commit_group;" ::: "memory");
        }

        for (int kc = 0; kc < NKC; kc++) {
            asm volatile("cp.async.wait_group 2;" ::: "memory");
            const char* A = myA + (kc % NSTAGE) * STAGE_B;

            float4 F[2][2];              // [row-half rr][k16 step s]
            #pragma unroll
            for (int s = 0; s < 2; s++) {
                int q0 = ((4 * s + t) ^ ((g & 1) << 2)) << 4;
                int q1 = ((4 * s + t) ^ (((g + 8) & 1) << 2)) << 4;  // same parity as g
                F[0][s] = *(const float4*)(A + g * 128 + q0);
                F[1][s] = *(const float4*)(A + (g + 8) * 128 + q1);
            }
            // refill this stage buf for chunk kc+3 (warp-private; reads above already issued)
            if (kc + NSTAGE < NKC)
                issue_stage(feat, rb, kc + NSTAGE, myA + (kc % NSTAGE) * STAGE_B, lane);
            asm volatile("cp.async.commit_group;" ::: "memory");

            uint32_t AH[2][2][2], AL[2][2][2];   // [rr][s][half]
            #pragma unroll
            for (int rr = 0; rr < 2; rr++)
                #pragma unroll
                for (int s = 0; s < 2; s++) {
                    split2(F[rr][s].x, F[rr][s].y, AH[rr][s][0], AL[rr][s][0]);
                    split2(F[rr][s].z, F[rr][s].w, AH[rr][s][1], AL[rr][s][1]);
                }

            const int boff = kc * 64 + t * 16;
            #pragma unroll
            for (int j = 0; j < 10; j++) {
                const int n = 8 * j + g;
                uint4 bh = *(const uint4*)(sm + SM_BHI + n * B_STRIDE + boff);
                uint4 bl = *(const uint4*)(sm + SM_BLO + n * B_STRIDE + boff);
                // k16 step 0: b pair (x, y)
                mma16816(c[j], AH[0][0][0], AH[1][0][0], AH[0][0][1], AH[1][0][1], bh.x, bh.y);
                mma16816(c[j], AH[0][0][0], AH[1][0][0], AH[0][0][1], AH[1][0][1], bl.x, bl.y);
                mma16816(c[j], AL[0][0][0], AL[1][0][0], AL[0][0][1], AL[1][0][1], bh.x, bh.y);
                // k16 step 1: b pair (z, w)
                mma16816(c[j], AH[0][1][0], AH[1][1][0], AH[0][1][1], AH[1][1][1], bh.z, bh.w);
                mma16816(c[j], AH[0][1][0], AH[1][1][0], AH[0][1][1], AH[1][1][1], bl.z, bl.w);
                mma16816(c[j], AL[0][1][0], AL[1][1][0], AL[0][1][1], AL[1][1][1], bh.z, bh.w);
            }
        }

        // ---- epilogue: bias + softmax + argmax; rows rb+g and rb+g+8 ----
        const size_t row0 = rb + g;
        const size_t row1 = rb + g + 8;
        float m0 = -INFINITY, m1 = -INFINITY;
        int i0 = 0, i1 = 0;
        #pragma unroll
        for (int j = 0; j < 10; j++) {
            #pragma unroll
            for (int h = 0; h < 2; h++) {
                int col = 8 * j + 2 * t + h;
                if (col < CLS) {
                    float v0 = c[j][h]     + bb[j][h];
                    float v1 = c[j][2 + h] + bb[j][h];
                    c[j][h]     = v0;
                    c[j][2 + h] = v1;
                    if (v0 > m0) { m0 = v0; i0 = col; }
                    if (v1 > m1) { m1 = v1; i1 = col; }
                }
            }
        }
        #pragma unroll
        for (int d = 1; d <= 2; d <<= 1) {
            float om0 = __shfl_xor_sync(full, m0, d);
            int   oi0 = __shfl_xor_sync(full, i0, d);
            if (om0 > m0 || (om0 == m0 && oi0 < i0)) { m0 = om0; i0 = oi0; }
            float om1 = __shfl_xor_sync(full, m1, d);
            int   oi1 = __shfl_xor_sync(full, i1, d);
            if (om1 > m1 || (om1 == m1 && oi1 < i1)) { m1 = om1; i1 = oi1; }
        }
        float s0 = 0.f, s1 = 0.f;
        #pragma unroll
        for (int j = 0; j < 10; j++) {
            #pragma unroll
            for (int h = 0; h < 2; h++) {
                int col = 8 * j + 2 * t + h;
                float e0 = 0.f, e1 = 0.f;
                if (col < CLS) {
                    e0 = __expf(c[j][h] - m0);
                    e1 = __expf(c[j][2 + h] - m1);
                }
                c[j][h] = e0; c[j][2 + h] = e1;
                s0 += e0; s1 += e1;
            }
        }
        #pragma unroll
        for (int d = 1; d <= 2; d <<= 1) {
            s0 += __shfl_xor_sync(full, s0, d);
            s1 += __shfl_xor_sync(full, s1, d);
        }
        const float v0inv = 1.0f / s0;
        const float v1inv = 1.0f / s1;
        #pragma unroll
        for (int j = 0; j < 10; j++) {
            int col = 8 * j + 2 * t;
            if (col < CLS) {  // skips only col 78 (j=9,t=3)
                *(float2*)(out + row0 * CLS + col) =
                    make_float2(c[j][0] * v0inv, c[j][1] * v0inv);
                *(float2*)(out + row1 * CLS + col) =
                    make_float2(c[j][2] * v1inv, c[j][3] * v1inv);
            }
        }
        if (t == 0) { g_best[row0] = i0; g_best[row1] = i1; }
    }
}

// ---------------------------------------------------------------------------
// CTC greedy decode: one warp per batch row, ballot compaction
// ---------------------------------------------------------------------------
__global__ void ctc_decode_kernel(float* __restrict__ out)
{
    const int gw = (blockIdx.x * blockDim.x + threadIdx.x) >> 5;
    const int lane = threadIdx.x & 31;
    const int wl = threadIdx.x >> 5;
    __shared__ float buf[8][32];
    if (gw >= BATCH) return;

    const int* bp = g_best + gw * TSTEPS;
    const unsigned full = 0xffffffffu;
    int v0 = bp[lane];
    int v1 = bp[lane + 32];
    int v2 = (lane < 16) ? bp[lane + 64] : BLANK;

    int p0 = __shfl_up_sync(full, v0, 1); if (lane == 0) p0 = -1;
    int t0 = __shfl_sync(full, v0, 31);
    int p1 = __shfl_up_sync(full, v1, 1); if (lane == 0) p1 = t0;
    int t1 = __shfl_sync(full, v1, 31);
    int p2 = __shfl_up_sync(full, v2, 1); if (lane == 0) p2 = t1;

    bool k0 = (v0 != BLANK) && (v0 != p0);
    bool k1 = (v1 != BLANK) && (v1 != p1);
    bool k2 = (lane < 16) && (v2 != BLANK) && (v2 != p2);
    unsigned m0 = __ballot_sync(full, k0);
    unsigned m1 = __ballot_sync(full, k1);
    unsigned m2 = __ballot_sync(full, k2);
    int c0 = __popc(m0), c1 = __popc(m1);
    unsigned lt = (1u << lane) - 1u;

    buf[wl][lane] = -1.0f;
    __syncwarp();
    if (k0) { int p = __popc(m0 & lt);           if (p < PRED_LEN) buf[wl][p] = (float)v0; }
    if (k1) { int p = c0 + __popc(m1 & lt);      if (p < PRED_LEN) buf[wl][p] = (float)v1; }
    if (k2) { int p = c0 + c1 + __popc(m2 & lt); if (p < PRED_LEN) buf[wl][p] = (float)v2; }
    __syncwarp();
    if (lane < PRED_LEN)
        out[(size_t)ROWS * CLS + (size_t)gw * PRED_LEN + lane] = buf[wl][lane];
}

// ---------------------------------------------------------------------------
extern "C" void kernel_launch(void* const* d_in, const int* in_sizes, int n_in,
                              void* d_out, int out_size)
{
    const float* feat = (const float*)d_in[0];
    const float* W    = (const float*)d_in[1];
    const float* b    = (const float*)d_in[2];
    float* out        = (float*)d_out;

    // reset dynamic work counter (graph-capturable memset node)
    void* ctr = nullptr;
    cudaGetSymbolAddress(&ctr, g_strip);
    cudaMemsetAsync(ctr, 0, sizeof(int));

    cudaFuncSetAttribute(ctc_main_kernel,
                         cudaFuncAttributeMaxDynamicSharedMemorySize, SM_TOTAL);
    ctc_main_kernel<<<NCTAS, THREADS, SM_TOTAL>>>(feat, W, b, out);
    ctc_decode_kernel<<<(BATCH * 32 + 255) / 256, 256>>>(out);
}

// round 7
// speedup vs baseline: 2.0555x; 1.1067x over previous
#include <cuda_runtime.h>
#include <cuda_bf16.h>
#include <cstdint>
#include <math.h>

// ---------------- problem constants ----------------
#define BATCH    1024
#define TSTEPS   80
#define DIM      512
#define CLS      78
#define BLANK    77
#define PRED_LEN 30
#define ROWS     (BATCH * TSTEPS)     // 81920

#define STRIP_M  16
#define NSTRIPS  (ROWS / STRIP_M)     // 5120
#define NCTAS    148
#define THREADS  384                  // 12 warps, each owns one 16-row strip at a time
#define NKC      16                   // k32 chunks (512/32)

// ---------------- smem layout (bytes) ----------------
#define B_STRIDE  1088                // 1024 data + 64 pad (conflict-free LDS.128)
#define B_BYTES   (80 * B_STRIDE)     // 87040 each (hi, lo)
#define SM_BHI    0
#define SM_BLO    B_BYTES
#define SM_BIAS   (2 * B_BYTES)       // 174080 : 80 floats
#define SM_TOTAL  (SM_BIAS + 320)     // 174400

__device__ int g_strip;               // dynamic work counter (reset each launch)
__device__ int g_best[ROWS];

// B k-permutation matched to A fragments held as 4-consecutive-k float4s:
// k -> u16 pos: grp=k>>5, r=k&31, s=r>>4, t=(r&15)>>2, idx=r&3
// pos = grp*32 + t*8 + s*4 + idx
__device__ __forceinline__ int kperm(int k) {
    int grp = k >> 5, r = k & 31;
    int s = r >> 4;
    int t = (r & 15) >> 2;
    int idx = r & 3;
    return grp * 32 + t * 8 + s * 4 + idx;
}

__device__ __forceinline__ uint32_t pack_bf16(float a, float b) {
    uint32_t r;
    asm("cvt.rn.satfinite.bf16x2.f32 %0, %1, %2;" : "=r"(r) : "f"(b), "f"(a));
    return r;
}

// split float pair into hi bf16x2 and lo bf16x2
__device__ __forceinline__ void split2(float a, float b, uint32_t& h, uint32_t& l) {
    h = pack_bf16(a, b);
    float ha = __uint_as_float(h << 16);
    float hb = __uint_as_float(h & 0xffff0000u);
    l = pack_bf16(a - ha, b - hb);
}

__device__ __forceinline__ void mma16816(float* c, uint32_t a0, uint32_t a1,
                                         uint32_t a2, uint32_t a3,
                                         uint32_t b0, uint32_t b1) {
    asm volatile(
        "mma.sync.aligned.m16n8k16.row.col.f32.bf16.bf16.f32 "
        "{%0,%1,%2,%3}, {%4,%5,%6,%7}, {%8,%9}, {%0,%1,%2,%3};"
        : "+f"(c[0]), "+f"(c[1]), "+f"(c[2]), "+f"(c[3])
        : "r"(a0), "r"(a1), "r"(a2), "r"(a3), "r"(b0), "r"(b1));
}

// ---------------------------------------------------------------------------
// Main: barrier-free, A loaded gmem->regs (no smem A), bf16-split HMMA
// ---------------------------------------------------------------------------
__global__ void __launch_bounds__(THREADS, 1)
ctc_main_kernel(const float* __restrict__ feat,
                const float* __restrict__ Wg,
                const float* __restrict__ bg,
                float* __restrict__ out)
{
    extern __shared__ char sm[];
    const int tid  = threadIdx.x;
    const int lane = tid & 31;
    const int g    = lane >> 2;
    const int t    = lane & 3;
    const unsigned full = 0xffffffffu;

    // ---- build B = W^T bf16 hi/lo, k-permuted, zero-padded to 80 cols ----
    for (int idx = tid; idx < 80 * DIM; idx += THREADS) {
        int k = idx / 80;
        int n = idx - k * 80;
        float v = (n < CLS) ? Wg[k * CLS + n] : 0.0f;
        __nv_bfloat16 h = __float2bfloat16_rn(v);
        __nv_bfloat16 l = __float2bfloat16_rn(v - __bfloat162float(h));
        int byte = n * B_STRIDE + kperm(k) * 2;
        *(uint16_t*)(sm + SM_BHI + byte) = __bfloat16_as_ushort(h);
        *(uint16_t*)(sm + SM_BLO + byte) = __bfloat16_as_ushort(l);
    }
    if (tid < 80) ((float*)(sm + SM_BIAS))[tid] = (tid < CLS) ? bg[tid] : 0.0f;
    __syncthreads();     // the ONLY cta-wide barrier
    const float* bias_sm = (const float*)(sm + SM_BIAS);

    for (;;) {
        int strip = 0;
        if (lane == 0) strip = atomicAdd(&g_strip, 1);
        strip = __shfl_sync(full, strip, 0);
        if (strip >= NSTRIPS) break;
        const size_t rb = (size_t)strip * STRIP_M;

        // per-thread A base: row rb+g, float4 column t
        const float4* a4 = (const float4*)(feat + (rb + g) * DIM) + t;

        float c[10][4];
        #pragma unroll
        for (int j = 0; j < 10; j++)
            { c[j][0] = 0.f; c[j][1] = 0.f; c[j][2] = 0.f; c[j][3] = 0.f; }

        // register ring: Fb[slot][rr][s], prefetch distance 2
        float4 Fb[2][2][2];
        #pragma unroll
        for (int p = 0; p < 2; p++)
            #pragma unroll
            for (int rr = 0; rr < 2; rr++)
                #pragma unroll
                for (int s = 0; s < 2; s++)
                    Fb[p][rr][s] = a4[rr * 8 * (DIM/4) + p * 8 + s * 4];

        #pragma unroll 2
        for (int kc = 0; kc < NKC; kc++) {
            const int slot = kc & 1;

            // convert this chunk's fp32 regs to bf16 hi/lo fragments
            uint32_t AH[2][2][2], AL[2][2][2];   // [rr][s][half]
            #pragma unroll
            for (int rr = 0; rr < 2; rr++)
                #pragma unroll
                for (int s = 0; s < 2; s++) {
                    split2(Fb[slot][rr][s].x, Fb[slot][rr][s].y, AH[rr][s][0], AL[rr][s][0]);
                    split2(Fb[slot][rr][s].z, Fb[slot][rr][s].w, AH[rr][s][1], AL[rr][s][1]);
                }

            // prefetch chunk kc+2 into the slot just freed
            if (kc + 2 < NKC) {
                #pragma unroll
                for (int rr = 0; rr < 2; rr++)
                    #pragma unroll
                    for (int s = 0; s < 2; s++)
                        Fb[slot][rr][s] = a4[rr * 8 * (DIM/4) + (kc + 2) * 8 + s * 4];
            }

            const int boff = kc * 64 + t * 16;
            #pragma unroll
            for (int j = 0; j < 10; j++) {
                const int n = 8 * j + g;
                uint4 bh = *(const uint4*)(sm + SM_BHI + n * B_STRIDE + boff);
                uint4 bl = *(const uint4*)(sm + SM_BLO + n * B_STRIDE + boff);
                // k16 step 0: b pair (x, y)
                mma16816(c[j], AH[0][0][0], AH[1][0][0], AH[0][0][1], AH[1][0][1], bh.x, bh.y);
                mma16816(c[j], AH[0][0][0], AH[1][0][0], AH[0][0][1], AH[1][0][1], bl.x, bl.y);
                mma16816(c[j], AL[0][0][0], AL[1][0][0], AL[0][0][1], AL[1][0][1], bh.x, bh.y);
                // k16 step 1: b pair (z, w)
                mma16816(c[j], AH[0][1][0], AH[1][1][0], AH[0][1][1], AH[1][1][1], bh.z, bh.w);
                mma16816(c[j], AH[0][1][0], AH[1][1][0], AH[0][1][1], AH[1][1][1], bl.z, bl.w);
                mma16816(c[j], AL[0][1][0], AL[1][1][0], AL[0][1][1], AL[1][1][1], bh.z, bh.w);
            }
        }

        // ---- epilogue: bias + softmax + argmax; rows rb+g and rb+g+8 ----
        float bb[10][2];
        #pragma unroll
        for (int j = 0; j < 10; j++) {
            float2 bv = *(const float2*)(bias_sm + 8 * j + 2 * t);
            bb[j][0] = bv.x; bb[j][1] = bv.y;
        }
        const size_t row0 = rb + g;
        const size_t row1 = rb + g + 8;
        float m0 = -INFINITY, m1 = -INFINITY;
        int i0 = 0, i1 = 0;
        #pragma unroll
        for (int j = 0; j < 10; j++) {
            #pragma unroll
            for (int h = 0; h < 2; h++) {
                int col = 8 * j + 2 * t + h;
                if (col < CLS) {
                    float v0 = c[j][h]     + bb[j][h];
                    float v1 = c[j][2 + h] + bb[j][h];
                    c[j][h]     = v0;
                    c[j][2 + h] = v1;
                    if (v0 > m0) { m0 = v0; i0 = col; }
                    if (v1 > m1) { m1 = v1; i1 = col; }
                }
            }
        }
        #pragma unroll
        for (int d = 1; d <= 2; d <<= 1) {
            float om0 = __shfl_xor_sync(full, m0, d);
            int   oi0 = __shfl_xor_sync(full, i0, d);
            if (om0 > m0 || (om0 == m0 && oi0 < i0)) { m0 = om0; i0 = oi0; }
            float om1 = __shfl_xor_sync(full, m1, d);
            int   oi1 = __shfl_xor_sync(full, i1, d);
            if (om1 > m1 || (om1 == m1 && oi1 < i1)) { m1 = om1; i1 = oi1; }
        }
        float s0 = 0.f, s1 = 0.f;
        #pragma unroll
        for (int j = 0; j < 10; j++) {
            #pragma unroll
            for (int h = 0; h < 2; h++) {
                int col = 8 * j + 2 * t + h;
                float e0 = 0.f, e1 = 0.f;
                if (col < CLS) {
                    e0 = __expf(c[j][h] - m0);
                    e1 = __expf(c[j][2 + h] - m1);
                }
                c[j][h] = e0; c[j][2 + h] = e1;
                s0 += e0; s1 += e1;
            }
        }
        #pragma unroll
        for (int d = 1; d <= 2; d <<= 1) {
            s0 += __shfl_xor_sync(full, s0, d);
            s1 += __shfl_xor_sync(full, s1, d);
        }
        const float v0inv = 1.0f / s0;
        const float v1inv = 1.0f / s1;
        #pragma unroll
        for (int j = 0; j < 10; j++) {
            int col = 8 * j + 2 * t;
            if (col < CLS) {  // skips only col 78 (j=9,t=3)
                *(float2*)(out + row0 * CLS + col) =
                    make_float2(c[j][0] * v0inv, c[j][1] * v0inv);
                *(float2*)(out + row1 * CLS + col) =
                    make_float2(c[j][2] * v1inv, c[j][3] * v1inv);
            }
        }
        if (t == 0) { g_best[row0] = i0; g_best[row1] = i1; }
    }
}

// ---------------------------------------------------------------------------
// CTC greedy decode: one warp per batch row, ballot compaction
// ---------------------------------------------------------------------------
__global__ void ctc_decode_kernel(float* __restrict__ out)
{
    const int gw = (blockIdx.x * blockDim.x + threadIdx.x) >> 5;
    const int lane = threadIdx.x & 31;
    const int wl = threadIdx.x >> 5;
    __shared__ float buf[8][32];
    if (gw >= BATCH) return;

    const int* bp = g_best + gw * TSTEPS;
    const unsigned full = 0xffffffffu;
    int v0 = bp[lane];
    int v1 = bp[lane + 32];
    int v2 = (lane < 16) ? bp[lane + 64] : BLANK;

    int p0 = __shfl_up_sync(full, v0, 1); if (lane == 0) p0 = -1;
    int t0 = __shfl_sync(full, v0, 31);
    int p1 = __shfl_up_sync(full, v1, 1); if (lane == 0) p1 = t0;
    int t1 = __shfl_sync(full, v1, 31);
    int p2 = __shfl_up_sync(full, v2, 1); if (lane == 0) p2 = t1;

    bool k0 = (v0 != BLANK) && (v0 != p0);
    bool k1 = (v1 != BLANK) && (v1 != p1);
    bool k2 = (lane < 16) && (v2 != BLANK) && (v2 != p2);
    unsigned m0 = __ballot_sync(full, k0);
    unsigned m1 = __ballot_sync(full, k1);
    unsigned m2 = __ballot_sync(full, k2);
    int c0 = __popc(m0), c1 = __popc(m1);
    unsigned lt = (1u << lane) - 1u;

    buf[wl][lane] = -1.0f;
    __syncwarp();
    if (k0) { int p = __popc(m0 & lt);           if (p < PRED_LEN) buf[wl][p] = (float)v0; }
    if (k1) { int p = c0 + __popc(m1 & lt);      if (p < PRED_LEN) buf[wl][p] = (float)v1; }
    if (k2) { int p = c0 + c1 + __popc(m2 & lt); if (p < PRED_LEN) buf[wl][p] = (float)v2; }
    __syncwarp();
    if (lane < PRED_LEN)
        out[(size_t)ROWS * CLS + (size_t)gw * PRED_LEN + lane] = buf[wl][lane];
}

// ---------------------------------------------------------------------------
extern "C" void kernel_launch(void* const* d_in, const int* in_sizes, int n_in,
                              void* d_out, int out_size)
{
    const float* feat = (const float*)d_in[0];
    const float* W    = (const float*)d_in[1];
    const float* b    = (const float*)d_in[2];
    float* out        = (float*)d_out;

    // reset dynamic work counter (graph-capturable memset node)
    void* ctr = nullptr;
    cudaGetSymbolAddress(&ctr, g_strip);
    cudaMemsetAsync(ctr, 0, sizeof(int));

    cudaFuncSetAttribute(ctc_main_kernel,
                         cudaFuncAttributeMaxDynamicSharedMemorySize, SM_TOTAL);
    ctc_main_kernel<<<NCTAS, THREADS, SM_TOTAL>>>(feat, W, b, out);
    ctc_decode_kernel<<<(BATCH * 32 + 255) / 256, 256>>>(out);
}

// round 8
// speedup vs baseline: 2.0722x; 1.0082x over previous
#include <cuda_runtime.h>
#include <cuda_bf16.h>
#include <cstdint>
#include <math.h>

// ---------------- problem constants ----------------
#define BATCH    1024
#define TSTEPS   80
#define DIM      512
#define CLS      78
#define BLANK    77
#define PRED_LEN 30
#define ROWS     (BATCH * TSTEPS)     // 81920

#define STRIP_M  16
#define NSTRIPS  (ROWS / STRIP_M)     // 5120
#define NCTAS    148
#define THREADS  384                  // 12 warps, each owns one 16-row strip at a time
#define NKC      16                   // k32 chunks (512/32)

// ---------------- smem layout (bytes) ----------------
#define B_STRIDE  1088                // 1024 data + 64 pad (conflict-free LDS.128)
#define B_BYTES   (80 * B_STRIDE)     // 87040 each (hi, lo)
#define SM_BHI    0
#define SM_BLO    B_BYTES
#define SM_BIAS   (2 * B_BYTES)       // 174080 : 80 floats
#define SM_TOTAL  (SM_BIAS + 320)     // 174400

__device__ int g_strip;               // dynamic work counter (reset each launch)
__device__ int g_best[ROWS];

// B k-permutation matched to A fragments held as 4-consecutive-k float4s:
// k -> u16 pos: grp=k>>5, r=k&31, s=r>>4, t=(r&15)>>2, idx=r&3
// pos = grp*32 + t*8 + s*4 + idx
__device__ __forceinline__ int kperm(int k) {
    int grp = k >> 5, r = k & 31;
    int s = r >> 4;
    int t = (r & 15) >> 2;
    int idx = r & 3;
    return grp * 32 + t * 8 + s * 4 + idx;
}

__device__ __forceinline__ uint32_t pack_bf16(float a, float b) {
    uint32_t r;
    asm("cvt.rn.satfinite.bf16x2.f32 %0, %1, %2;" : "=r"(r) : "f"(b), "f"(a));
    return r;
}

// split float pair into hi bf16x2 and lo bf16x2
__device__ __forceinline__ void split2(float a, float b, uint32_t& h, uint32_t& l) {
    h = pack_bf16(a, b);
    float ha = __uint_as_float(h << 16);
    float hb = __uint_as_float(h & 0xffff0000u);
    l = pack_bf16(a - ha, b - hb);
}

__device__ __forceinline__ void mma16816(float* c, uint32_t a0, uint32_t a1,
                                         uint32_t a2, uint32_t a3,
                                         uint32_t b0, uint32_t b1) {
    asm volatile(
        "mma.sync.aligned.m16n8k16.row.col.f32.bf16.bf16.f32 "
        "{%0,%1,%2,%3}, {%4,%5,%6,%7}, {%8,%9}, {%0,%1,%2,%3};"
        : "+f"(c[0]), "+f"(c[1]), "+f"(c[2]), "+f"(c[3])
        : "r"(a0), "r"(a1), "r"(a2), "r"(a3), "r"(b0), "r"(b1));
}

// ---------------------------------------------------------------------------
// Main: barrier-free, A loaded gmem->regs, bf16-split HMMA, j-pair interleave
// ---------------------------------------------------------------------------
__global__ void __launch_bounds__(THREADS, 1)
ctc_main_kernel(const float* __restrict__ feat,
                const float* __restrict__ Wg,
                const float* __restrict__ bg,
                float* __restrict__ out)
{
    extern __shared__ char sm[];
    const int tid  = threadIdx.x;
    const int lane = tid & 31;
    const int g    = lane >> 2;
    const int t    = lane & 3;
    const unsigned full = 0xffffffffu;

    // ---- build B = W^T bf16 hi/lo, k-permuted, zero-padded to 80 cols ----
    for (int idx = tid; idx < 80 * DIM; idx += THREADS) {
        int k = idx / 80;
        int n = idx - k * 80;
        float v = (n < CLS) ? Wg[k * CLS + n] : 0.0f;
        __nv_bfloat16 h = __float2bfloat16_rn(v);
        __nv_bfloat16 l = __float2bfloat16_rn(v - __bfloat162float(h));
        int byte = n * B_STRIDE + kperm(k) * 2;
        *(uint16_t*)(sm + SM_BHI + byte) = __bfloat16_as_ushort(h);
        *(uint16_t*)(sm + SM_BLO + byte) = __bfloat16_as_ushort(l);
    }
    if (tid < 80) ((float*)(sm + SM_BIAS))[tid] = (tid < CLS) ? bg[tid] : 0.0f;
    __syncthreads();     // the ONLY cta-wide barrier
    const float* bias_sm = (const float*)(sm + SM_BIAS);

    for (;;) {
        int strip = 0;
        if (lane == 0) strip = atomicAdd(&g_strip, 1);
        strip = __shfl_sync(full, strip, 0);
        if (strip >= NSTRIPS) break;
        const size_t rb = (size_t)strip * STRIP_M;

        // per-thread A base: row rb+g, float4 column t
        const float4* a4 = (const float4*)(feat + (rb + g) * DIM) + t;

        float c[10][4];
        #pragma unroll
        for (int j = 0; j < 10; j++)
            { c[j][0] = 0.f; c[j][1] = 0.f; c[j][2] = 0.f; c[j][3] = 0.f; }

        // register ring: Fb[slot][rr][s], prefetch distance 2
        float4 Fb[2][2][2];
        #pragma unroll
        for (int p = 0; p < 2; p++)
            #pragma unroll
            for (int rr = 0; rr < 2; rr++)
                #pragma unroll
                for (int s = 0; s < 2; s++)
                    Fb[p][rr][s] = a4[rr * 8 * (DIM/4) + p * 8 + s * 4];

        #pragma unroll 2
        for (int kc = 0; kc < NKC; kc++) {
            const int slot = kc & 1;

            // convert this chunk's fp32 regs to bf16 hi/lo fragments
            uint32_t AH[2][2][2], AL[2][2][2];   // [rr][s][half]
            #pragma unroll
            for (int rr = 0; rr < 2; rr++)
                #pragma unroll
                for (int s = 0; s < 2; s++) {
                    split2(Fb[slot][rr][s].x, Fb[slot][rr][s].y, AH[rr][s][0], AL[rr][s][0]);
                    split2(Fb[slot][rr][s].z, Fb[slot][rr][s].w, AH[rr][s][1], AL[rr][s][1]);
                }

            // prefetch chunk kc+2 into the slot just freed
            if (kc + 2 < NKC) {
                #pragma unroll
                for (int rr = 0; rr < 2; rr++)
                    #pragma unroll
                    for (int s = 0; s < 2; s++)
                        Fb[slot][rr][s] = a4[rr * 8 * (DIM/4) + (kc + 2) * 8 + s * 4];
            }

            const int boff = kc * 64 + t * 16;
            // j-pair interleave: alternate accumulators to break RAW chains
            #pragma unroll
            for (int jp = 0; jp < 5; jp++) {
                const int n0 = 16 * jp + g;
                const int n1 = n0 + 8;
                uint4 bh0 = *(const uint4*)(sm + SM_BHI + n0 * B_STRIDE + boff);
                uint4 bl0 = *(const uint4*)(sm + SM_BLO + n0 * B_STRIDE + boff);
                uint4 bh1 = *(const uint4*)(sm + SM_BHI + n1 * B_STRIDE + boff);
                uint4 bl1 = *(const uint4*)(sm + SM_BLO + n1 * B_STRIDE + boff);
                float* c0 = c[2 * jp];
                float* c1 = c[2 * jp + 1];
                // HH, step 0/1, alternating c0/c1
                mma16816(c0, AH[0][0][0], AH[1][0][0], AH[0][0][1], AH[1][0][1], bh0.x, bh0.y);
                mma16816(c1, AH[0][0][0], AH[1][0][0], AH[0][0][1], AH[1][0][1], bh1.x, bh1.y);
                mma16816(c0, AH[0][1][0], AH[1][1][0], AH[0][1][1], AH[1][1][1], bh0.z, bh0.w);
                mma16816(c1, AH[0][1][0], AH[1][1][0], AH[0][1][1], AH[1][1][1], bh1.z, bh1.w);
                // HL
                mma16816(c0, AH[0][0][0], AH[1][0][0], AH[0][0][1], AH[1][0][1], bl0.x, bl0.y);
                mma16816(c1, AH[0][0][0], AH[1][0][0], AH[0][0][1], AH[1][0][1], bl1.x, bl1.y);
                mma16816(c0, AH[0][1][0], AH[1][1][0], AH[0][1][1], AH[1][1][1], bl0.z, bl0.w);
                mma16816(c1, AH[0][1][0], AH[1][1][0], AH[0][1][1], AH[1][1][1], bl1.z, bl1.w);
                // LH
                mma16816(c0, AL[0][0][0], AL[1][0][0], AL[0][0][1], AL[1][0][1], bh0.x, bh0.y);
                mma16816(c1, AL[0][0][0], AL[1][0][0], AL[0][0][1], AL[1][0][1], bh1.x, bh1.y);
                mma16816(c0, AL[0][1][0], AL[1][1][0], AL[0][1][1], AL[1][1][1], bh0.z, bh0.w);
                mma16816(c1, AL[0][1][0], AL[1][1][0], AL[0][1][1], AL[1][1][1], bh1.z, bh1.w);
            }
        }

        // ---- epilogue: bias + softmax + argmax; rows rb+g and rb+g+8 ----
        float bb[10][2];
        #pragma unroll
        for (int j = 0; j < 10; j++) {
            float2 bv = *(const float2*)(bias_sm + 8 * j + 2 * t);
            bb[j][0] = bv.x; bb[j][1] = bv.y;
        }
        const size_t row0 = rb + g;
        const size_t row1 = rb + g + 8;
        float m0 = -INFINITY, m1 = -INFINITY;
        int i0 = 0, i1 = 0;
        #pragma unroll
        for (int j = 0; j < 10; j++) {
            #pragma unroll
            for (int h = 0; h < 2; h++) {
                int col = 8 * j + 2 * t + h;
                if (col < CLS) {
                    float v0 = c[j][h]     + bb[j][h];
                    float v1 = c[j][2 + h] + bb[j][h];
                    c[j][h]     = v0;
                    c[j][2 + h] = v1;
                    if (v0 > m0) { m0 = v0; i0 = col; }
                    if (v1 > m1) { m1 = v1; i1 = col; }
                }
            }
        }
        #pragma unroll
        for (int d = 1; d <= 2; d <<= 1) {
            float om0 = __shfl_xor_sync(full, m0, d);
            int   oi0 = __shfl_xor_sync(full, i0, d);
            if (om0 > m0 || (om0 == m0 && oi0 < i0)) { m0 = om0; i0 = oi0; }
            float om1 = __shfl_xor_sync(full, m1, d);
            int   oi1 = __shfl_xor_sync(full, i1, d);
            if (om1 > m1 || (om1 == m1 && oi1 < i1)) { m1 = om1; i1 = oi1; }
        }
        float s0 = 0.f, s1 = 0.f;
        #pragma unroll
        for (int j = 0; j < 10; j++) {
            #pragma unroll
            for (int h = 0; h < 2; h++) {
                int col = 8 * j + 2 * t + h;
                float e0 = 0.f, e1 = 0.f;
                if (col < CLS) {
                    e0 = __expf(c[j][h] - m0);
                    e1 = __expf(c[j][2 + h] - m1);
                }
                c[j][h] = e0; c[j][2 + h] = e1;
                s0 += e0; s1 += e1;
            }
        }
        #pragma unroll
        for (int d = 1; d <= 2; d <<= 1) {
            s0 += __shfl_xor_sync(full, s0, d);
            s1 += __shfl_xor_sync(full, s1, d);
        }
        const float v0inv = 1.0f / s0;
        const float v1inv = 1.0f / s1;
        #pragma unroll
        for (int j = 0; j < 10; j++) {
            int col = 8 * j + 2 * t;
            if (col < CLS) {  // skips only col 78 (j=9,t=3)
                *(float2*)(out + row0 * CLS + col) =
                    make_float2(c[j][0] * v0inv, c[j][1] * v0inv);
                *(float2*)(out + row1 * CLS + col) =
                    make_float2(c[j][2] * v1inv, c[j][3] * v1inv);
            }
        }
        if (t == 0) { g_best[row0] = i0; g_best[row1] = i1; }
    }
}

// ---------------------------------------------------------------------------
// CTC greedy decode: one warp per batch row, ballot compaction
// ---------------------------------------------------------------------------
__global__ void ctc_decode_kernel(float* __restrict__ out)
{
    const int gw = (blockIdx.x * blockDim.x + threadIdx.x) >> 5;
    const int lane = threadIdx.x & 31;
    const int wl = threadIdx.x >> 5;
    __shared__ float buf[8][32];
    if (gw >= BATCH) return;

    const int* bp = g_best + gw * TSTEPS;
    const unsigned full = 0xffffffffu;
    int v0 = bp[lane];
    int v1 = bp[lane + 32];
    int v2 = (lane < 16) ? bp[lane + 64] : BLANK;

    int p0 = __shfl_up_sync(full, v0, 1); if (lane == 0) p0 = -1;
    int t0 = __shfl_sync(full, v0, 31);
    int p1 = __shfl_up_sync(full, v1, 1); if (lane == 0) p1 = t0;
    int t1 = __shfl_sync(full, v1, 31);
    int p2 = __shfl_up_sync(full, v2, 1); if (lane == 0) p2 = t1;

    bool k0 = (v0 != BLANK) && (v0 != p0);
    bool k1 = (v1 != BLANK) && (v1 != p1);
    bool k2 = (lane < 16) && (v2 != BLANK) && (v2 != p2);
    unsigned m0 = __ballot_sync(full, k0);
    unsigned m1 = __ballot_sync(full, k1);
    unsigned m2 = __ballot_sync(full, k2);
    int c0 = __popc(m0), c1 = __popc(m1);
    unsigned lt = (1u << lane) - 1u;

    buf[wl][lane] = -1.0f;
    __syncwarp();
    if (k0) { int p = __popc(m0 & lt);           if (p < PRED_LEN) buf[wl][p] = (float)v0; }
    if (k1) { int p = c0 + __popc(m1 & lt);      if (p < PRED_LEN) buf[wl][p] = (float)v1; }
    if (k2) { int p = c0 + c1 + __popc(m2 & lt); if (p < PRED_LEN) buf[wl][p] = (float)v2; }
    __syncwarp();
    if (lane < PRED_LEN)
        out[(size_t)ROWS * CLS + (size_t)gw * PRED_LEN + lane] = buf[wl][lane];
}

// ---------------------------------------------------------------------------
// counter reset as a kernel (also shifts ncu launch parity so launch #6 = main)
__global__ void reset_counter_kernel() { g_strip = 0; }
__global__ void pad_kernel() {}

// ---------------------------------------------------------------------------
extern "C" void kernel_launch(void* const* d_in, const int* in_sizes, int n_in,
                              void* d_out, int out_size)
{
    const float* feat = (const float*)d_in[0];
    const float* W    = (const float*)d_in[1];
    const float* b    = (const float*)d_in[2];
    float* out        = (float*)d_out;

    reset_counter_kernel<<<1, 1>>>();

    cudaFuncSetAttribute(ctc_main_kernel,
                         cudaFuncAttributeMaxDynamicSharedMemorySize, SM_TOTAL);
    ctc_main_kernel<<<NCTAS, THREADS, SM_TOTAL>>>(feat, W, b, out);
    ctc_decode_kernel<<<(BATCH * 32 + 255) / 256, 256>>>(out);
    pad_kernel<<<1, 1>>>();
}

// round 9
// speedup vs baseline: 2.1335x; 1.0296x over previous
#include <cuda_runtime.h>
#include <cuda_bf16.h>
#include <cstdint>
#include <math.h>

// ---------------- problem constants ----------------
#define BATCH    1024
#define TSTEPS   80
#define DIM      512
#define CLS      78
#define BLANK    77
#define PRED_LEN 30
#define ROWS     (BATCH * TSTEPS)     // 81920

#define ITEMS_PER_CTA 7
#define NCTAS    147                  // 146*7 + 2 = 1024
#define THREADS  384                  // 12 warps
#define STRIP_M  16
#define NKC      16                   // k32 chunks (512/32)

// ---------------- smem layout (bytes) ----------------
#define B_STRIDE  1088                // 1024 data + 64 pad (conflict-free LDS.128)
#define B_BYTES   (80 * B_STRIDE)     // 87040 each (hi, lo)
#define SM_BHI    0
#define SM_BLO    B_BYTES
#define SM_BIAS   (2 * B_BYTES)       // 174080 : 80 floats
#define SM_SBEST  (SM_BIAS + 320)     // 174400 : int sbest[7*80]
#define SM_CTR    (SM_SBEST + 2240)   // 176640 : int counter
#define SM_TOTAL  (SM_CTR + 16)       // 176656

// B k-permutation matched to A fragments held as 4-consecutive-k float4s:
// k -> u16 pos: grp=k>>5, r=k&31, s=r>>4, t=(r&15)>>2, idx=r&3
__device__ __forceinline__ int kperm(int k) {
    int grp = k >> 5, r = k & 31;
    int s = r >> 4;
    int t = (r & 15) >> 2;
    int idx = r & 3;
    return grp * 32 + t * 8 + s * 4 + idx;
}

__device__ __forceinline__ uint32_t pack_bf16(float a, float b) {
    uint32_t r;
    asm("cvt.rn.satfinite.bf16x2.f32 %0, %1, %2;" : "=r"(r) : "f"(b), "f"(a));
    return r;
}

// split float pair into hi bf16x2 and lo bf16x2
__device__ __forceinline__ void split2(float a, float b, uint32_t& h, uint32_t& l) {
    h = pack_bf16(a, b);
    float ha = __uint_as_float(h << 16);
    float hb = __uint_as_float(h & 0xffff0000u);
    l = pack_bf16(a - ha, b - hb);
}

__device__ __forceinline__ void mma16816(float* c, uint32_t a0, uint32_t a1,
                                         uint32_t a2, uint32_t a3,
                                         uint32_t b0, uint32_t b1) {
    asm volatile(
        "mma.sync.aligned.m16n8k16.row.col.f32.bf16.bf16.f32 "
        "{%0,%1,%2,%3}, {%4,%5,%6,%7}, {%8,%9}, {%0,%1,%2,%3};"
        : "+f"(c[0]), "+f"(c[1]), "+f"(c[2]), "+f"(c[3])
        : "r"(a0), "r"(a1), "r"(a2), "r"(a3), "r"(b0), "r"(b1));
}

// ---------------------------------------------------------------------------
// Single kernel: GEMM (bf16-split HMMA) + bias + softmax + argmax + CTC decode
// ---------------------------------------------------------------------------
__global__ void __launch_bounds__(THREADS, 1)
ctc_fused_kernel(const float* __restrict__ feat,
                 const float* __restrict__ Wg,
                 const float* __restrict__ bg,
                 float* __restrict__ out)
{
    extern __shared__ char sm[];
    const int tid  = threadIdx.x;
    const int lane = tid & 31;
    const int warp = tid >> 5;
    const int g    = lane >> 2;
    const int t    = lane & 3;
    const unsigned full = 0xffffffffu;

    const int it0     = blockIdx.x * ITEMS_PER_CTA;
    const int nitems  = min(ITEMS_PER_CTA, BATCH - it0);
    const int nstrips = nitems * (TSTEPS / STRIP_M);     // 5 strips per item
    int* const sctr   = (int*)(sm + SM_CTR);
    int* const sbest  = (int*)(sm + SM_SBEST);

    if (tid == 0) *sctr = 0;

    // ---- build B = W^T bf16 hi/lo, k-permuted, zero-padded to 80 cols ----
    for (int idx = tid; idx < 80 * DIM; idx += THREADS) {
        int k = idx / 80;
        int n = idx - k * 80;
        float v = (n < CLS) ? Wg[k * CLS + n] : 0.0f;
        __nv_bfloat16 h = __float2bfloat16_rn(v);
        __nv_bfloat16 l = __float2bfloat16_rn(v - __bfloat162float(h));
        int byte = n * B_STRIDE + kperm(k) * 2;
        *(uint16_t*)(sm + SM_BHI + byte) = __bfloat16_as_ushort(h);
        *(uint16_t*)(sm + SM_BLO + byte) = __bfloat16_as_ushort(l);
    }
    if (tid < 80) ((float*)(sm + SM_BIAS))[tid] = (tid < CLS) ? bg[tid] : 0.0f;
    __syncthreads();
    const float* bias_sm = (const float*)(sm + SM_BIAS);

    for (;;) {
        int ls = 0;
        if (lane == 0) ls = atomicAdd(sctr, 1);
        ls = __shfl_sync(full, ls, 0);
        if (ls >= nstrips) break;
        const size_t rb = (size_t)it0 * TSTEPS + (size_t)ls * STRIP_M;

        // per-thread A base: row rb+g, float4 column t
        const float4* a4 = (const float4*)(feat + (rb + g) * DIM) + t;

        float c[10][4];
        #pragma unroll
        for (int j = 0; j < 10; j++)
            { c[j][0] = 0.f; c[j][1] = 0.f; c[j][2] = 0.f; c[j][3] = 0.f; }

        // register ring: Fb[slot][rr][s], prefetch distance 2
        float4 Fb[2][2][2];
        #pragma unroll
        for (int p = 0; p < 2; p++)
            #pragma unroll
            for (int rr = 0; rr < 2; rr++)
                #pragma unroll
                for (int s = 0; s < 2; s++)
                    Fb[p][rr][s] = a4[rr * 8 * (DIM/4) + p * 8 + s * 4];

        #pragma unroll 2
        for (int kc = 0; kc < NKC; kc++) {
            const int slot = kc & 1;

            uint32_t AH[2][2][2], AL[2][2][2];   // [rr][s][half]
            #pragma unroll
            for (int rr = 0; rr < 2; rr++)
                #pragma unroll
                for (int s = 0; s < 2; s++) {
                    split2(Fb[slot][rr][s].x, Fb[slot][rr][s].y, AH[rr][s][0], AL[rr][s][0]);
                    split2(Fb[slot][rr][s].z, Fb[slot][rr][s].w, AH[rr][s][1], AL[rr][s][1]);
                }

            if (kc + 2 < NKC) {
                #pragma unroll
                for (int rr = 0; rr < 2; rr++)
                    #pragma unroll
                    for (int s = 0; s < 2; s++)
                        Fb[slot][rr][s] = a4[rr * 8 * (DIM/4) + (kc + 2) * 8 + s * 4];
            }

            const int boff = kc * 64 + t * 16;
            #pragma unroll
            for (int jp = 0; jp < 5; jp++) {
                const int n0 = 16 * jp + g;
                const int n1 = n0 + 8;
                uint4 bh0 = *(const uint4*)(sm + SM_BHI + n0 * B_STRIDE + boff);
                uint4 bl0 = *(const uint4*)(sm + SM_BLO + n0 * B_STRIDE + boff);
                uint4 bh1 = *(const uint4*)(sm + SM_BHI + n1 * B_STRIDE + boff);
                uint4 bl1 = *(const uint4*)(sm + SM_BLO + n1 * B_STRIDE + boff);
                float* c0 = c[2 * jp];
                float* c1 = c[2 * jp + 1];
                mma16816(c0, AH[0][0][0], AH[1][0][0], AH[0][0][1], AH[1][0][1], bh0.x, bh0.y);
                mma16816(c1, AH[0][0][0], AH[1][0][0], AH[0][0][1], AH[1][0][1], bh1.x, bh1.y);
                mma16816(c0, AH[0][1][0], AH[1][1][0], AH[0][1][1], AH[1][1][1], bh0.z, bh0.w);
                mma16816(c1, AH[0][1][0], AH[1][1][0], AH[0][1][1], AH[1][1][1], bh1.z, bh1.w);
                mma16816(c0, AH[0][0][0], AH[1][0][0], AH[0][0][1], AH[1][0][1], bl0.x, bl0.y);
                mma16816(c1, AH[0][0][0], AH[1][0][0], AH[0][0][1], AH[1][0][1], bl1.x, bl1.y);
                mma16816(c0, AH[0][1][0], AH[1][1][0], AH[0][1][1], AH[1][1][1], bl0.z, bl0.w);
                mma16816(c1, AH[0][1][0], AH[1][1][0], AH[0][1][1], AH[1][1][1], bl1.z, bl1.w);
                mma16816(c0, AL[0][0][0], AL[1][0][0], AL[0][0][1], AL[1][0][1], bh0.x, bh0.y);
                mma16816(c1, AL[0][0][0], AL[1][0][0], AL[0][0][1], AL[1][0][1], bh1.x, bh1.y);
                mma16816(c0, AL[0][1][0], AL[1][1][0], AL[0][1][1], AL[1][1][1], bh0.z, bh0.w);
                mma16816(c1, AL[0][1][0], AL[1][1][0], AL[0][1][1], AL[1][1][1], bh1.z, bh1.w);
            }
        }

        // ---- epilogue: bias + softmax + argmax; rows rb+g and rb+g+8 ----
        float bb[10][2];
        #pragma unroll
        for (int j = 0; j < 10; j++) {
            float2 bv = *(const float2*)(bias_sm + 8 * j + 2 * t);
            bb[j][0] = bv.x; bb[j][1] = bv.y;
        }
        const size_t row0 = rb + g;
        const size_t row1 = rb + g + 8;
        float m0 = -INFINITY, m1 = -INFINITY;
        int i0 = 0, i1 = 0;
        #pragma unroll
        for (int j = 0; j < 10; j++) {
            #pragma unroll
            for (int h = 0; h < 2; h++) {
                int col = 8 * j + 2 * t + h;
                if (col < CLS) {
                    float v0 = c[j][h]     + bb[j][h];
                    float v1 = c[j][2 + h] + bb[j][h];
                    c[j][h]     = v0;
                    c[j][2 + h] = v1;
                    if (v0 > m0) { m0 = v0; i0 = col; }
                    if (v1 > m1) { m1 = v1; i1 = col; }
                }
            }
        }
        #pragma unroll
        for (int d = 1; d <= 2; d <<= 1) {
            float om0 = __shfl_xor_sync(full, m0, d);
            int   oi0 = __shfl_xor_sync(full, i0, d);
            if (om0 > m0 || (om0 == m0 && oi0 < i0)) { m0 = om0; i0 = oi0; }
            float om1 = __shfl_xor_sync(full, m1, d);
            int   oi1 = __shfl_xor_sync(full, i1, d);
            if (om1 > m1 || (om1 == m1 && oi1 < i1)) { m1 = om1; i1 = oi1; }
        }
        float s0 = 0.f, s1 = 0.f;
        #pragma unroll
        for (int j = 0; j < 10; j++) {
            #pragma unroll
            for (int h = 0; h < 2; h++) {
                int col = 8 * j + 2 * t + h;
                float e0 = 0.f, e1 = 0.f;
                if (col < CLS) {
                    e0 = __expf(c[j][h] - m0);
                    e1 = __expf(c[j][2 + h] - m1);
                }
                c[j][h] = e0; c[j][2 + h] = e1;
                s0 += e0; s1 += e1;
            }
        }
        #pragma unroll
        for (int d = 1; d <= 2; d <<= 1) {
            s0 += __shfl_xor_sync(full, s0, d);
            s1 += __shfl_xor_sync(full, s1, d);
        }
        const float v0inv = 1.0f / s0;
        const float v1inv = 1.0f / s1;
        #pragma unroll
        for (int j = 0; j < 10; j++) {
            int col = 8 * j + 2 * t;
            if (col < CLS) {  // skips only col 78 (j=9,t=3)
                *(float2*)(out + row0 * CLS + col) =
                    make_float2(c[j][0] * v0inv, c[j][1] * v0inv);
                *(float2*)(out + row1 * CLS + col) =
                    make_float2(c[j][2] * v1inv, c[j][3] * v1inv);
            }
        }
        if (t == 0) {
            sbest[ls * STRIP_M + g]     = i0;
            sbest[ls * STRIP_M + g + 8] = i1;
        }
    }

    // ---- all strips of this CTA done -> in-CTA CTC greedy decode ----
    __syncthreads();
    if (warp < nitems) {
        const int* bp = sbest + warp * TSTEPS;
        int v0 = bp[lane];
        int v1 = bp[lane + 32];
        int v2 = (lane < 16) ? bp[lane + 64] : BLANK;

        int p0 = __shfl_up_sync(full, v0, 1); if (lane == 0) p0 = -1;
        int t0 = __shfl_sync(full, v0, 31);
        int p1 = __shfl_up_sync(full, v1, 1); if (lane == 0) p1 = t0;
        int t1 = __shfl_sync(full, v1, 31);
        int p2 = __shfl_up_sync(full, v2, 1); if (lane == 0) p2 = t1;

        bool k0 = (v0 != BLANK) && (v0 != p0);
        bool k1 = (v1 != BLANK) && (v1 != p1);
        bool k2 = (lane < 16) && (v2 != BLANK) && (v2 != p2);
        unsigned m0 = __ballot_sync(full, k0);
        unsigned m1 = __ballot_sync(full, k1);
        unsigned m2 = __ballot_sync(full, k2);
        int c0 = __popc(m0), c1 = __popc(m1);
        unsigned lt = (1u << lane) - 1u;

        float* ob = out + (size_t)ROWS * CLS + (size_t)(it0 + warp) * PRED_LEN;
        if (lane < PRED_LEN) ob[lane] = -1.0f;
        __syncwarp();
        if (k0) { int p = __popc(m0 & lt);           if (p < PRED_LEN) ob[p] = (float)v0; }
        if (k1) { int p = c0 + __popc(m1 & lt);      if (p < PRED_LEN) ob[p] = (float)v1; }
        if (k2) { int p = c0 + c1 + __popc(m2 & lt); if (p < PRED_LEN) ob[p] = (float)v2; }
    }
}

// ---------------------------------------------------------------------------
extern "C" void kernel_launch(void* const* d_in, const int* in_sizes, int n_in,
                              void* d_out, int out_size)
{
    const float* feat = (const float*)d_in[0];
    const float* W    = (const float*)d_in[1];
    const float* b    = (const float*)d_in[2];
    float* out        = (float*)d_out;

    cudaFuncSetAttribute(ctc_fused_kernel,
                         cudaFuncAttributeMaxDynamicSharedMemorySize, SM_TOTAL);
    ctc_fused_kernel<<<NCTAS, THREADS, SM_TOTAL>>>(feat, W, b, out);
}